// round 9
// baseline (speedup 1.0000x reference)
#include <cuda_runtime.h>
#include <cuda_bf16.h>
#include <mma.h>
#include <math.h>

#define N_NODES 50000
#define N_EDGES 800000
#define DD 32
#define HH 64
#define L_LAYERS 4
#define SPR 264          // padded smem row stride for 256-edge fp32 tiles (floats)

typedef unsigned long long ull;
typedef unsigned int uint;
typedef unsigned short ushort;

using namespace nvcuda;

// ---------------- scratch ----------------
__device__ float g_h[(size_t)N_NODES * DD];
__device__ float g_e[L_LAYERS + 1][(size_t)N_EDGES * DD];
__device__ float g_agg[(size_t)N_NODES * DD];
// pre-split rel weights (hi/lo bf16), row-major identical to source layout
__device__ ushort g_w1h[4 * 6144], g_w1l[4 * 6144];
__device__ ushort g_w2h[4 * 4096], g_w2l[4 * 4096];
__device__ ushort g_w3h[4 * 2048], g_w3l[4 * 2048];

// ---------------- packed fp32x2 helpers ----------------
__device__ __forceinline__ ull pack2(float a, float b) {
    ull r; asm("mov.b64 %0,{%1,%2};" : "=l"(r) : "f"(a), "f"(b)); return r;
}
__device__ __forceinline__ float2 unpack2(ull v) {
    float2 r; asm("mov.b64 {%0,%1},%2;" : "=f"(r.x), "=f"(r.y) : "l"(v)); return r;
}
__device__ __forceinline__ void fma2(ull& d, ull a, ull b) {
    asm("fma.rn.f32x2 %0,%1,%2,%0;" : "+l"(d) : "l"(a), "l"(b));
}
__device__ __forceinline__ void red_add_v2(float* p, float x, float y) {
    asm volatile("red.global.add.v2.f32 [%0], {%1,%2};" :: "l"(p), "f"(x), "f"(y) : "memory");
}
__device__ __forceinline__ void coop_load(float* dst, const float* src, int n, int t, int nt) {
    for (int i = t; i < n; i += nt) dst[i] = src[i];
}

// ---------------- bf16 split helpers ----------------
__device__ __forceinline__ uint pack_bf16x2(float lo, float hi) {
    uint r; asm("cvt.rn.bf16x2.f32 %0, %1, %2;" : "=r"(r) : "f"(hi), "f"(lo)); return r;
}
__device__ __forceinline__ void split2(float x, float y, uint& h2, uint& l2) {
    h2 = pack_bf16x2(x, y);
    float hx = __uint_as_float(h2 << 16);
    float hy = __uint_as_float(h2 & 0xFFFF0000u);
    l2 = pack_bf16x2(x - hx, y - hy);
}
__device__ __forceinline__ void split1(float v, ushort& h, ushort& l) {
    asm("cvt.rn.bf16.f32 %0, %1;" : "=h"(h) : "f"(v));
    float hf = __uint_as_float((uint)h << 16);
    float r = v - hf;
    asm("cvt.rn.bf16.f32 %0, %1;" : "=h"(l) : "f"(r));
}

// ---------------- weight prep (once): elementwise bf16 split ----------------
__global__ void prep_w_kernel(const float* __restrict__ rW1,
                              const float* __restrict__ rW2,
                              const float* __restrict__ rW3) {
    int i = blockIdx.x * 256 + threadIdx.x;
    if (i >= 4 * 12288) return;
    int l = i / 12288, j = i % 12288;
    ushort h, lo;
    if (j < 6144) {
        split1(rW1[(size_t)l * 6144 + j], h, lo);
        g_w1h[l * 6144 + j] = h; g_w1l[l * 6144 + j] = lo;
    } else if (j < 10240) {
        int q = j - 6144;
        split1(rW2[(size_t)l * 4096 + q], h, lo);
        g_w2h[l * 4096 + q] = h; g_w2l[l * 4096 + q] = lo;
    } else {
        int q = j - 10240;
        split1(rW3[(size_t)l * 2048 + q], h, lo);
        g_w3h[l * 2048 + q] = h; g_w3l[l * 2048 + q] = lo;
    }
}

// ================= wmma relational kernel (v2) =================
// block = 128 edges, 256 threads (8 warps), 2 blocks/SM.
// A hi/lo in smem [128][112] bf16; C f32 [128][72]; B fragments straight from global.
#define RA_STRIDE 112
#define RC_STRIDE 72
#define R_B1   0
#define R_B2   256
#define R_B3   512
#define R_AHI  1024
#define R_ALO  (R_AHI + 128 * RA_STRIDE * 2)      // 29696
#define R_C    (R_ALO + 128 * RA_STRIDE * 2)      // 58368
#define R_SMEM (R_C + 128 * RC_STRIDE * 4)        // 95232

__global__ __launch_bounds__(256, 2) void rel_wmma_kernel(const int* __restrict__ ei, int layer,
        const float* __restrict__ b1, const float* __restrict__ b2, const float* __restrict__ b3) {
    extern __shared__ char smem[];
    float* sb1 = (float*)(smem + R_B1);
    float* sb2 = (float*)(smem + R_B2);
    float* sb3 = (float*)(smem + R_B3);
    __nv_bfloat16* Ah = (__nv_bfloat16*)(smem + R_AHI);
    __nv_bfloat16* Al = (__nv_bfloat16*)(smem + R_ALO);
    float* Cf = (float*)(smem + R_C);

    const __nv_bfloat16* w1h = (const __nv_bfloat16*)(g_w1h + layer * 6144);
    const __nv_bfloat16* w1l = (const __nv_bfloat16*)(g_w1l + layer * 6144);
    const __nv_bfloat16* w2h = (const __nv_bfloat16*)(g_w2h + layer * 4096);
    const __nv_bfloat16* w2l = (const __nv_bfloat16*)(g_w2l + layer * 4096);
    const __nv_bfloat16* w3h = (const __nv_bfloat16*)(g_w3h + layer * 2048);
    const __nv_bfloat16* w3l = (const __nv_bfloat16*)(g_w3l + layer * 2048);

    int t = threadIdx.x;
    int wid = t >> 5;
    int blk = blockIdx.x * 128;

    if (t < 64) sb1[t] = b1[t];
    else if (t < 128) sb2[t - 64] = b2[t - 64];
    else if (t < 160) sb3[t - 128] = b3[t - 128];

    // ---- activation gather + split (2 threads/edge, chunked, low regs) ----
    {
        int e = t >> 1, half = t & 1;
        int eid = blk + e;
        int s = ei[eid];
        int dn = ei[N_EDGES + eid];
        uint* AhU = (uint*)Ah;
        uint* AlU = (uint*)Al;
        int base = e * (RA_STRIDE / 2) + half * 24;
        if (half == 0) {
            const float4* hd = (const float4*)(g_h + (size_t)dn * DD);
            const float4* hs = (const float4*)(g_h + (size_t)s * DD);
#pragma unroll
            for (int q = 0; q < 8; q++) {
                float4 w = hd[q];
                uint h2, l2;
                split2(w.x, w.y, h2, l2); AhU[base + 2*q] = h2; AlU[base + 2*q] = l2;
                split2(w.z, w.w, h2, l2); AhU[base + 2*q + 1] = h2; AlU[base + 2*q + 1] = l2;
            }
#pragma unroll
            for (int q = 0; q < 4; q++) {
                float4 w = hs[q];
                uint h2, l2;
                split2(w.x, w.y, h2, l2); AhU[base + 16 + 2*q] = h2; AlU[base + 16 + 2*q] = l2;
                split2(w.z, w.w, h2, l2); AhU[base + 16 + 2*q + 1] = h2; AlU[base + 16 + 2*q + 1] = l2;
            }
        } else {
            const float4* hs = (const float4*)(g_h + (size_t)s * DD);
            const float4* ep = (const float4*)(g_e[layer] + (size_t)eid * DD);
#pragma unroll
            for (int q = 0; q < 4; q++) {
                float4 w = hs[4 + q];
                uint h2, l2;
                split2(w.x, w.y, h2, l2); AhU[base + 2*q] = h2; AlU[base + 2*q] = l2;
                split2(w.z, w.w, h2, l2); AhU[base + 2*q + 1] = h2; AlU[base + 2*q + 1] = l2;
            }
#pragma unroll
            for (int q = 0; q < 8; q++) {
                float4 w = ep[q];
                uint h2, l2;
                split2(w.x, w.y, h2, l2); AhU[base + 8 + 2*q] = h2; AlU[base + 8 + 2*q] = l2;
                split2(w.z, w.w, h2, l2); AhU[base + 8 + 2*q + 1] = h2; AlU[base + 8 + 2*q + 1] = l2;
            }
        }
    }
    __syncthreads();

    int m0 = wid * 16;

    // ---- layer 1: C = A[128x96] @ W1[96x64] (B fragments from global) ----
    {
        wmma::fragment<wmma::accumulator, 16, 16, 16, float> acc[4];
#pragma unroll
        for (int n = 0; n < 4; n++) wmma::fill_fragment(acc[n], 0.f);
#pragma unroll
        for (int kt = 0; kt < 6; kt++) {
            wmma::fragment<wmma::matrix_a, 16, 16, 16, __nv_bfloat16, wmma::row_major> aH, aL;
            wmma::load_matrix_sync(aH, Ah + m0 * RA_STRIDE + kt * 16, RA_STRIDE);
            wmma::load_matrix_sync(aL, Al + m0 * RA_STRIDE + kt * 16, RA_STRIDE);
#pragma unroll
            for (int n = 0; n < 4; n++) {
                wmma::fragment<wmma::matrix_b, 16, 16, 16, __nv_bfloat16, wmma::row_major> bH, bL;
                wmma::load_matrix_sync(bH, w1h + kt * 16 * 64 + n * 16, 64);
                wmma::load_matrix_sync(bL, w1l + kt * 16 * 64 + n * 16, 64);
                wmma::mma_sync(acc[n], aH, bH, acc[n]);
                wmma::mma_sync(acc[n], aH, bL, acc[n]);
                wmma::mma_sync(acc[n], aL, bH, acc[n]);
            }
        }
#pragma unroll
        for (int n = 0; n < 4; n++)
            wmma::store_matrix_sync(Cf + m0 * RC_STRIDE + n * 16, acc[n], RC_STRIDE, wmma::mem_row_major);
    }
    __syncthreads();

    // ---- bias + relu + split -> A (64 cols) ----
    {
        int r = t >> 1, c0 = (t & 1) * 32;
        uint* AhU = (uint*)Ah;
        uint* AlU = (uint*)Al;
        int base = r * (RA_STRIDE / 2) + c0 / 2;
#pragma unroll
        for (int c2 = 0; c2 < 16; c2++) {
            int col = c0 + 2 * c2;
            float x = fmaxf(Cf[r * RC_STRIDE + col] + sb1[col], 0.f);
            float y = fmaxf(Cf[r * RC_STRIDE + col + 1] + sb1[col + 1], 0.f);
            uint h2, l2; split2(x, y, h2, l2);
            AhU[base + c2] = h2;
            AlU[base + c2] = l2;
        }
    }
    __syncthreads();

    // ---- layer 2: C = A[128x64] @ W2[64x64] ----
    {
        wmma::fragment<wmma::accumulator, 16, 16, 16, float> acc[4];
#pragma unroll
        for (int n = 0; n < 4; n++) wmma::fill_fragment(acc[n], 0.f);
#pragma unroll
        for (int kt = 0; kt < 4; kt++) {
            wmma::fragment<wmma::matrix_a, 16, 16, 16, __nv_bfloat16, wmma::row_major> aH, aL;
            wmma::load_matrix_sync(aH, Ah + m0 * RA_STRIDE + kt * 16, RA_STRIDE);
            wmma::load_matrix_sync(aL, Al + m0 * RA_STRIDE + kt * 16, RA_STRIDE);
#pragma unroll
            for (int n = 0; n < 4; n++) {
                wmma::fragment<wmma::matrix_b, 16, 16, 16, __nv_bfloat16, wmma::row_major> bH, bL;
                wmma::load_matrix_sync(bH, w2h + kt * 16 * 64 + n * 16, 64);
                wmma::load_matrix_sync(bL, w2l + kt * 16 * 64 + n * 16, 64);
                wmma::mma_sync(acc[n], aH, bH, acc[n]);
                wmma::mma_sync(acc[n], aH, bL, acc[n]);
                wmma::mma_sync(acc[n], aL, bH, acc[n]);
            }
        }
        __syncthreads();   // layer-1 C consumed before overwrite
#pragma unroll
        for (int n = 0; n < 4; n++)
            wmma::store_matrix_sync(Cf + m0 * RC_STRIDE + n * 16, acc[n], RC_STRIDE, wmma::mem_row_major);
    }
    __syncthreads();

    // ---- bias + relu + split -> A ----
    {
        int r = t >> 1, c0 = (t & 1) * 32;
        uint* AhU = (uint*)Ah;
        uint* AlU = (uint*)Al;
        int base = r * (RA_STRIDE / 2) + c0 / 2;
#pragma unroll
        for (int c2 = 0; c2 < 16; c2++) {
            int col = c0 + 2 * c2;
            float x = fmaxf(Cf[r * RC_STRIDE + col] + sb2[col], 0.f);
            float y = fmaxf(Cf[r * RC_STRIDE + col + 1] + sb2[col + 1], 0.f);
            uint h2, l2; split2(x, y, h2, l2);
            AhU[base + c2] = h2;
            AlU[base + c2] = l2;
        }
    }
    __syncthreads();

    // ---- layer 3: C = A[128x64] @ W3[64x32] ----
    {
        wmma::fragment<wmma::accumulator, 16, 16, 16, float> acc[2];
#pragma unroll
        for (int n = 0; n < 2; n++) wmma::fill_fragment(acc[n], 0.f);
#pragma unroll
        for (int kt = 0; kt < 4; kt++) {
            wmma::fragment<wmma::matrix_a, 16, 16, 16, __nv_bfloat16, wmma::row_major> aH, aL;
            wmma::load_matrix_sync(aH, Ah + m0 * RA_STRIDE + kt * 16, RA_STRIDE);
            wmma::load_matrix_sync(aL, Al + m0 * RA_STRIDE + kt * 16, RA_STRIDE);
#pragma unroll
            for (int n = 0; n < 2; n++) {
                wmma::fragment<wmma::matrix_b, 16, 16, 16, __nv_bfloat16, wmma::row_major> bH, bL;
                wmma::load_matrix_sync(bH, w3h + kt * 16 * 32 + n * 16, 32);
                wmma::load_matrix_sync(bL, w3l + kt * 16 * 32 + n * 16, 32);
                wmma::mma_sync(acc[n], aH, bH, acc[n]);
                wmma::mma_sync(acc[n], aH, bL, acc[n]);
                wmma::mma_sync(acc[n], aL, bH, acc[n]);
            }
        }
        __syncthreads();   // layer-2 C consumed
#pragma unroll
        for (int n = 0; n < 2; n++)
            wmma::store_matrix_sync(Cf + m0 * RC_STRIDE + n * 16, acc[n], RC_STRIDE, wmma::mem_row_major);
    }
    __syncthreads();

    // ---- epilogue (chunked): e_out = 0.5 e_in + 0.5 e_new ; agg[dst] += e_new ----
    if (t < 128) {
        int eid = blk + t;
        int dn = ei[N_EDGES + eid];
        const float4* ep = (const float4*)(g_e[layer] + (size_t)eid * DD);
        float* eo = g_e[layer + 1] + (size_t)eid * DD;
        float* ag = g_agg + (size_t)dn * DD;
#pragma unroll
        for (int q = 0; q < 8; q++) {
            int c = 4 * q;
            float e0 = Cf[t * RC_STRIDE + c]     + sb3[c];
            float e1 = Cf[t * RC_STRIDE + c + 1] + sb3[c + 1];
            float e2 = Cf[t * RC_STRIDE + c + 2] + sb3[c + 2];
            float e3 = Cf[t * RC_STRIDE + c + 3] + sb3[c + 3];
            float4 ein = ep[q];
            float4 o;
            o.x = 0.5f * ein.x + 0.5f * e0;
            o.y = 0.5f * ein.y + 0.5f * e1;
            o.z = 0.5f * ein.z + 0.5f * e2;
            o.w = 0.5f * ein.w + 0.5f * e3;
            *(float4*)&eo[c] = o;
            red_add_v2(&ag[c], e0, e1);
            red_add_v2(&ag[c + 2], e2, e3);
        }
    }
}

// ================= fp32 tiled kernels (unchanged, known good) =================

__device__ __forceinline__ void st4col(float* smT, int row, int e, float4 v) {
    smT[(row + 0) * SPR + e] = v.x;
    smT[(row + 1) * SPR + e] = v.y;
    smT[(row + 2) * SPR + e] = v.z;
    smT[(row + 3) * SPR + e] = v.w;
}
template <int NU>
__device__ __forceinline__ void tile_fma(float4 a, const ull* __restrict__ wp, ull acc[4][NU]) {
    ull w[NU];
#pragma unroll
    for (int j = 0; j < NU; j++) w[j] = wp[j];
    ull a0 = pack2(a.x, a.x), a1 = pack2(a.y, a.y), a2 = pack2(a.z, a.z), a3 = pack2(a.w, a.w);
#pragma unroll
    for (int j = 0; j < NU; j++) {
        fma2(acc[0][j], a0, w[j]);
        fma2(acc[1][j], a1, w[j]);
        fma2(acc[2][j], a2, w[j]);
        fma2(acc[3][j], a3, w[j]);
    }
}
template <int NU>
__device__ __forceinline__ void init_bias(ull acc[4][NU], const float* b, int base) {
#pragma unroll
    for (int j = 0; j < NU; j++) {
        ull bj = pack2(b[base + 2 * j], b[base + 2 * j + 1]);
#pragma unroll
        for (int i = 0; i < 4; i++) acc[i][j] = bj;
    }
}
template <int NU>
__device__ __forceinline__ void init_zero_t(ull acc[4][NU]) {
#pragma unroll
    for (int j = 0; j < NU; j++)
#pragma unroll
        for (int i = 0; i < 4; i++) acc[i][j] = 0ull;
}
__device__ __forceinline__ float relu_sel(ull v, int hi) {
    float2 f = unpack2(v); return fmaxf(hi ? f.y : f.x, 0.f);
}
__device__ __forceinline__ void relu_writeT16(float* smT, ull acc[4][8], int og, int eg) {
#pragma unroll
    for (int cc = 0; cc < 16; cc++) {
        int j = cc >> 1, hi = cc & 1;
        float4 v;
        v.x = relu_sel(acc[0][j], hi);
        v.y = relu_sel(acc[1][j], hi);
        v.z = relu_sel(acc[2][j], hi);
        v.w = relu_sel(acc[3][j], hi);
        *(float4*)&smT[(og * 16 + cc) * SPR + 4 * eg] = v;
    }
}
template <int K, int NU>
__device__ __forceinline__ void mma_loop(const float* smT, const float* W, int wld, int wo,
                                         int eg, ull acc[4][NU]) {
#pragma unroll 2
    for (int k = 0; k < K; k++) {
        float4 a = *(const float4*)&smT[k * SPR + 4 * eg];
        tile_fma<NU>(a, (const ull*)&W[k * wld + wo], acc);
    }
}
template <int OUTP>
__device__ __forceinline__ void consume1(float a, const float* Wrow, ull* acc) {
    ull a2 = pack2(a, a);
    const ull* w = reinterpret_cast<const ull*>(Wrow);
#pragma unroll
    for (int j = 0; j < OUTP; j++) fma2(acc[j], a2, w[j]);
}
template <int OUTP>
__device__ __forceinline__ void init_zero(ull* acc) {
#pragma unroll
    for (int j = 0; j < OUTP; j++) acc[j] = 0ull;
}
template <int OUTP>
__device__ __forceinline__ void relu_store(const ull* acc, ull* s) {
#pragma unroll
    for (int j = 0; j < OUTP; j++) {
        float2 v = unpack2(acc[j]);
        s[j * 128] = pack2(fmaxf(v.x, 0.f), fmaxf(v.y, 0.f));
    }
}
template <int INP, int OUTP>
__device__ __forceinline__ void mlp_scratch(const ull* s, const float* W, ull* acc) {
#pragma unroll 1
    for (int p = 0; p < INP; p++) {
        float2 av = unpack2(s[p * 128]);
        consume1<OUTP>(av.x, W + (size_t)(2 * p) * (2 * OUTP), acc);
        consume1<OUTP>(av.y, W + (size_t)(2 * p + 1) * (2 * OUTP), acc);
    }
}

__global__ __launch_bounds__(128) void node_enc_kernel(const float* __restrict__ x,
                                                       const float* __restrict__ W1,
                                                       const float* __restrict__ W2) {
    extern __shared__ float sm[];
    float* sW1 = sm;
    float* sW2 = sm + 896;
    ull* scr = (ull*)(sm + 2944);
    int t = threadIdx.x;
    coop_load(sW1, W1, 896, t, 128);
    coop_load(sW2, W2, 2048, t, 128);
    __syncthreads();
    int n = blockIdx.x * 128 + t;
    if (n >= N_NODES) return;
    const float* xr = x + (size_t)n * 14;
    ull acc[32]; init_zero<32>(acc);
#pragma unroll 1
    for (int k = 0; k < 14; k++) consume1<32>(xr[k], sW1 + k * 64, acc);
    relu_store<32>(acc, scr + t);
    ull acc2[16]; init_zero<16>(acc2);
    mlp_scratch<32, 16>(scr + t, sW2, acc2);
    float4* ho = (float4*)(g_h + (size_t)n * DD);
#pragma unroll
    for (int q = 0; q < 8; q++) {
        float2 v0 = unpack2(acc2[2 * q]);
        float2 v1 = unpack2(acc2[2 * q + 1]);
        float4 o;
        o.x = fmaxf(v0.x, 0.f); o.y = fmaxf(v0.y, 0.f);
        o.z = fmaxf(v1.x, 0.f); o.w = fmaxf(v1.y, 0.f);
        ho[q] = o;
    }
}

__global__ __launch_bounds__(256, 2) void edge_enc_tile_kernel(const float* __restrict__ ea,
                                                               const float* __restrict__ W1,
                                                               const float* __restrict__ W2) {
    extern __shared__ float sm[];
    float* sW1 = sm;
    float* sW2 = sm + 256;
    float* smT = sm + 2304;
    int t = threadIdx.x;
    coop_load(sW1, W1, 256, t, 256);
    coop_load(sW2, W2, 2048, t, 256);
    int blk = blockIdx.x * 256;
    {
        float4 av = ((const float4*)ea)[blk + t];
        st4col(smT, 0, t, av);
    }
    __syncthreads();
    int eg = t & 63, og = t >> 6;
    ull acc[4][8];
    init_zero_t<8>(acc);
    mma_loop<4, 8>(smT, sW1, 64, og * 16, eg, acc);
    __syncthreads();
    relu_writeT16(smT, acc, og, eg);
    __syncthreads();
    ull acc3[4][4];
    init_zero_t<4>(acc3);
    mma_loop<64, 4>(smT, sW2, 32, og * 8, eg, acc3);
#pragma unroll
    for (int i = 0; i < 4; i++) {
        int eid_i = blk + 4 * eg + i;
#pragma unroll
        for (int j = 0; j < 4; j++) {
            int c = og * 8 + 2 * j;
            float2 v = unpack2(acc3[i][j]);
            float2 o; o.x = fmaxf(v.x, 0.f); o.y = fmaxf(v.y, 0.f);
            *(float2*)&g_e[0][(size_t)eid_i * DD + c] = o;
        }
    }
}

__global__ __launch_bounds__(256, 2) void obj_tile_kernel(const float* __restrict__ W1, const float* __restrict__ b1,
        const float* __restrict__ W2, const float* __restrict__ b2,
        const float* __restrict__ W3, const float* __restrict__ b3) {
    extern __shared__ float sm[];
    float* sW1 = sm;
    float* sW2 = sm + 4096;
    float* sW3 = sm + 8192;
    float* sb1 = sm + 10240;
    float* sb2 = sm + 10304;
    float* sb3 = sm + 10368;
    float* smT = sm + 10400;
    int t = threadIdx.x;
    coop_load(sW1, W1, 4096, t, 256);
    coop_load(sW2, W2, 4096, t, 256);
    coop_load(sW3, W3, 2048, t, 256);
    coop_load(sb1, b1, 64, t, 256);
    coop_load(sb2, b2, 64, t, 256);
    coop_load(sb3, b3, 32, t, 256);
    int blk = blockIdx.x * 256;
    {
        int n = blk + t;
        if (n < N_NODES) {
            const float4* hp = (const float4*)(g_h + (size_t)n * DD);
            const float4* ap = (const float4*)(g_agg + (size_t)n * DD);
#pragma unroll
            for (int q = 0; q < 8; q++) st4col(smT, 4 * q, t, hp[q]);
#pragma unroll
            for (int q = 0; q < 8; q++) st4col(smT, 32 + 4 * q, t, ap[q]);
        }
    }
    __syncthreads();
    int eg = t & 63, og = t >> 6;
    ull acc[4][8];
    init_bias<8>(acc, sb1, og * 16);
    mma_loop<64, 8>(smT, sW1, 64, og * 16, eg, acc);
    __syncthreads();
    relu_writeT16(smT, acc, og, eg);
    __syncthreads();
    init_bias<8>(acc, sb2, og * 16);
    mma_loop<64, 8>(smT, sW2, 64, og * 16, eg, acc);
    __syncthreads();
    relu_writeT16(smT, acc, og, eg);
    __syncthreads();
    ull acc3[4][4];
    init_bias<4>(acc3, sb3, og * 8);
    mma_loop<64, 4>(smT, sW3, 32, og * 8, eg, acc3);
#pragma unroll
    for (int i = 0; i < 4; i++) {
        int n_i = blk + 4 * eg + i;
        if (n_i < N_NODES) {
#pragma unroll
            for (int j = 0; j < 4; j++) {
                int c = og * 8 + 2 * j;
                float2 v = unpack2(acc3[i][j]);
                float2 hold = *(float2*)&g_h[(size_t)n_i * DD + c];
                float2 o;
                o.x = 0.5f * hold.x + 0.5f * v.x;
                o.y = 0.5f * hold.y + 0.5f * v.y;
                *(float2*)&g_h[(size_t)n_i * DD + c] = o;
            }
        }
    }
}

__global__ __launch_bounds__(256, 1) void final_tile_kernel(const int* __restrict__ ei,
        const float* __restrict__ W1, const float* __restrict__ b1,
        const float* __restrict__ W2, const float* __restrict__ b2,
        const float* __restrict__ W3, const float* __restrict__ b3,
        float* __restrict__ out) {
    extern __shared__ float sm[];
    float* sW1 = sm;
    float* sW2 = sm + 6144;
    float* sW3 = sm + 10240;
    float* sb1 = sm + 10304;
    float* sb2 = sm + 10368;
    float* sb3 = sm + 10432;
    float* smT = sm + 10436;
    int t = threadIdx.x;
    coop_load(sW1, W1, 6144, t, 256);
    coop_load(sW2, W2, 4096, t, 256);
    coop_load(sW3, W3, 64, t, 256);
    coop_load(sb1, b1, 64, t, 256);
    coop_load(sb2, b2, 64, t, 256);
    if (t == 0) sb3[0] = b3[0];
    int blk = blockIdx.x * 256;
    int eid = blk + t;
    int s = ei[eid];
    int d = ei[N_EDGES + eid];
    {
        const float4* hs = (const float4*)(g_h + (size_t)s * DD);
        const float4* hd = (const float4*)(g_h + (size_t)d * DD);
        const float4* e1 = (const float4*)(g_e[1] + (size_t)eid * DD);
#pragma unroll
        for (int q = 0; q < 8; q++) st4col(smT, 4 * q, t, hs[q]);
#pragma unroll
        for (int q = 0; q < 8; q++) st4col(smT, 32 + 4 * q, t, hd[q]);
#pragma unroll
        for (int q = 0; q < 8; q++) st4col(smT, 64 + 4 * q, t, e1[q]);
    }
    __syncthreads();
    int eg = t & 63, og = t >> 6;
    ull acc[4][8];
    init_bias<8>(acc, sb1, og * 16);
    mma_loop<96, 8>(smT, sW1, 64, og * 16, eg, acc);
    __syncthreads();
    {
        const float4* e2 = (const float4*)(g_e[2] + (size_t)eid * DD);
        const float4* e3 = (const float4*)(g_e[3] + (size_t)eid * DD);
        const float4* e4 = (const float4*)(g_e[4] + (size_t)eid * DD);
#pragma unroll
        for (int q = 0; q < 8; q++) st4col(smT, 4 * q, t, e2[q]);
#pragma unroll
        for (int q = 0; q < 8; q++) st4col(smT, 32 + 4 * q, t, e3[q]);
#pragma unroll
        for (int q = 0; q < 8; q++) st4col(smT, 64 + 4 * q, t, e4[q]);
    }
    coop_load(sW1, W1 + 96 * 64, 6144, t, 256);
    __syncthreads();
    mma_loop<96, 8>(smT, sW1, 64, og * 16, eg, acc);
    __syncthreads();
    relu_writeT16(smT, acc, og, eg);
    __syncthreads();
    init_bias<8>(acc, sb2, og * 16);
    mma_loop<64, 8>(smT, sW2, 64, og * 16, eg, acc);
    __syncthreads();
    relu_writeT16(smT, acc, og, eg);
    __syncthreads();
    {
        float logit = sb3[0];
#pragma unroll 2
        for (int k = 0; k < 64; k++) logit += smT[k * SPR + t] * sW3[k];
        float sig = 1.f / (1.f + expf(-logit));
        out[eid] = 1e-3f + (1.f - 2e-3f) * sig;
    }
}

__global__ void zero_agg_kernel() {
    int i = blockIdx.x * 256 + threadIdx.x;
    if (i < N_NODES * DD) g_agg[i] = 0.f;
}

__global__ void writeback_kernel(float* __restrict__ out) {
    size_t i = (size_t)blockIdx.x * 256 + threadIdx.x;
    if (i < (size_t)N_NODES * DD) out[(size_t)N_EDGES + i] = g_h[i];
    if (i < (size_t)N_EDGES * DD) out[(size_t)N_EDGES + (size_t)N_NODES * DD + i] = g_e[4][i];
}

// ---------------- launch ----------------
extern "C" void kernel_launch(void* const* d_in, const int* in_sizes, int n_in,
                              void* d_out, int out_size) {
    const float* x      = (const float*)d_in[0];
    const int*   ei     = (const int*)d_in[1];
    const float* ea     = (const float*)d_in[2];
    const float* enW1   = (const float*)d_in[3];
    const float* enW2   = (const float*)d_in[4];
    const float* eeW1   = (const float*)d_in[5];
    const float* eeW2   = (const float*)d_in[6];
    const float* rW1    = (const float*)d_in[7];
    const float* rb1    = (const float*)d_in[8];
    const float* rW2    = (const float*)d_in[9];
    const float* rb2    = (const float*)d_in[10];
    const float* rW3    = (const float*)d_in[11];
    const float* rb3    = (const float*)d_in[12];
    const float* oW1    = (const float*)d_in[13];
    const float* ob1    = (const float*)d_in[14];
    const float* oW2    = (const float*)d_in[15];
    const float* ob2    = (const float*)d_in[16];
    const float* oW3    = (const float*)d_in[17];
    const float* ob3    = (const float*)d_in[18];
    const float* wW1    = (const float*)d_in[19];
    const float* wb1    = (const float*)d_in[20];
    const float* wW2    = (const float*)d_in[21];
    const float* wb2    = (const float*)d_in[22];
    const float* wW3    = (const float*)d_in[23];
    const float* wb3    = (const float*)d_in[24];
    float* out = (float*)d_out;

    const int NODE_SMEM = 2944 * 4 + 128 * 32 * 8;
    const int EE_SMEM   = (2304 + 64 * SPR) * 4;
    const int OBJ_SMEM  = (10400 + 64 * SPR) * 4;
    const int FIN_SMEM  = (10436 + 96 * SPR) * 4;

    cudaFuncSetAttribute(node_enc_kernel, cudaFuncAttributeMaxDynamicSharedMemorySize, NODE_SMEM);
    cudaFuncSetAttribute(edge_enc_tile_kernel, cudaFuncAttributeMaxDynamicSharedMemorySize, EE_SMEM);
    cudaFuncSetAttribute(rel_wmma_kernel, cudaFuncAttributeMaxDynamicSharedMemorySize, R_SMEM);
    cudaFuncSetAttribute(obj_tile_kernel, cudaFuncAttributeMaxDynamicSharedMemorySize, OBJ_SMEM);
    cudaFuncSetAttribute(final_tile_kernel, cudaFuncAttributeMaxDynamicSharedMemorySize, FIN_SMEM);

    int nodeBlocks = (N_NODES + 127) / 128;
    int objBlocks  = (N_NODES + 255) / 256;
    int tileBlocks256 = N_EDGES / 256;     // 3125
    int relBlocks = N_EDGES / 128;         // 6250

    prep_w_kernel<<<(4 * 12288 + 255) / 256, 256>>>(rW1, rW2, rW3);
    node_enc_kernel<<<nodeBlocks, 128, NODE_SMEM>>>(x, enW1, enW2);
    edge_enc_tile_kernel<<<tileBlocks256, 256, EE_SMEM>>>(ea, eeW1, eeW2);

    for (int l = 0; l < L_LAYERS; l++) {
        zero_agg_kernel<<<(N_NODES * DD + 255) / 256, 256>>>();
        rel_wmma_kernel<<<relBlocks, 256, R_SMEM>>>(ei, l,
            rb1 + (size_t)l * 64, rb2 + (size_t)l * 64, rb3 + (size_t)l * 32);
        obj_tile_kernel<<<objBlocks, 256, OBJ_SMEM>>>(
            oW1 + (size_t)l * 64 * 64, ob1 + (size_t)l * 64,
            oW2 + (size_t)l * 64 * 64, ob2 + (size_t)l * 64,
            oW3 + (size_t)l * 64 * 32, ob3 + (size_t)l * 32);
    }

    final_tile_kernel<<<tileBlocks256, 256, FIN_SMEM>>>(ei, wW1, wb1, wW2, wb2, wW3, wb3, out);

    writeback_kernel<<<((size_t)N_EDGES * DD + 255) / 256, 256>>>(out);
}

// round 10
// speedup vs baseline: 1.3469x; 1.3469x over previous
#include <cuda_runtime.h>
#include <math.h>

#define N_NODES 50000
#define N_EDGES 800000
#define DD 32
#define HH 64
#define L_LAYERS 4
#define SP 136           // padded smem row stride for 128-edge fp32 tiles (final kernel)
#define SPW 260          // rel kernel row stride: 260%4==0 (16B rows) and 65 mod 8 = 1 -> conflict-free lane-row STS.128

typedef unsigned long long ull;

// ---------------- scratch ----------------
__device__ float g_h[(size_t)N_NODES * DD];
__device__ float g_e[L_LAYERS + 1][(size_t)N_EDGES * DD];
__device__ float g_agg[(size_t)N_NODES * DD];

// ---------------- packed fp32x2 helpers ----------------
__device__ __forceinline__ ull pack2(float a, float b) {
    ull r; asm("mov.b64 %0,{%1,%2};" : "=l"(r) : "f"(a), "f"(b)); return r;
}
__device__ __forceinline__ float2 unpack2(ull v) {
    float2 r; asm("mov.b64 {%0,%1},%2;" : "=f"(r.x), "=f"(r.y) : "l"(v)); return r;
}
__device__ __forceinline__ void fma2(ull& d, ull a, ull b) {
    asm("fma.rn.f32x2 %0,%1,%2,%0;" : "+l"(d) : "l"(a), "l"(b));
}
__device__ __forceinline__ void red_add_v2(float* p, float x, float y) {
    asm volatile("red.global.add.v2.f32 [%0], {%1,%2};" :: "l"(p), "f"(x), "f"(y) : "memory");
}
__device__ __forceinline__ void coop_load(float* dst, const float* src, int n, int t, int nt) {
    for (int i = t; i < n; i += nt) dst[i] = src[i];
}

// =====================================================================
// NEW relational kernel: warp-private columns, outputs-per-lane, weights
// streamed from global (L1-hot). 256 threads / 256 edges per block.
// smem: smT[96][SPW] floats only (97.5KB) -> 2 blocks/SM, no __syncthreads.
// =====================================================================
__device__ __forceinline__ void st4colW(float* smT, int row, int c, float4 v) {
    smT[(row + 0) * SPW + c] = v.x;
    smT[(row + 1) * SPW + c] = v.y;
    smT[(row + 2) * SPW + c] = v.z;
    smT[(row + 3) * SPW + c] = v.w;
}

__global__ __launch_bounds__(256, 2) void rel_gemm_kernel(const int* __restrict__ ei, int layer,
        const float* __restrict__ W1, const float* __restrict__ b1,
        const float* __restrict__ W2, const float* __restrict__ b2,
        const float* __restrict__ W3, const float* __restrict__ b3) {
    extern __shared__ float smT[];   // [96][SPW]
    int t = threadIdx.x;
    int wid = t >> 5;
    int l = t & 31;
    int blk = blockIdx.x * 256;
    int eid = blk + t;

    int s = ei[eid];
    int dn = ei[N_EDGES + eid];

    // ---- gather: thread t fills column t (rows 0..95) ----
    {
        const float4* hd = (const float4*)(g_h + (size_t)dn * DD);
        const float4* hs = (const float4*)(g_h + (size_t)s * DD);
        const float4* ep = (const float4*)(g_e[layer] + (size_t)eid * DD);
#pragma unroll
        for (int q = 0; q < 8; q++) st4colW(smT, 4 * q, t, hd[q]);
#pragma unroll
        for (int q = 0; q < 8; q++) st4colW(smT, 32 + 4 * q, t, hs[q]);
#pragma unroll
        for (int q = 0; q < 8; q++) st4colW(smT, 64 + 4 * q, t, ep[q]);
    }
    __syncwarp();

    int ebase = wid * 32;                  // this warp's 32 edge columns
    const float* base = smT + ebase;

    // ---- layer 1: K=96, lane owns outs l and l+32 ----
    ull accL[16], accH[16];
#pragma unroll
    for (int j = 0; j < 16; j++) { accL[j] = 0ull; accH[j] = 0ull; }
#pragma unroll 2
    for (int k = 0; k < 96; k++) {
        float wl = W1[k * 64 + l];
        float wh = W1[k * 64 + 32 + l];
        ull wL = pack2(wl, wl), wH = pack2(wh, wh);
        const ulonglong2* ar = (const ulonglong2*)(base + k * SPW);
#pragma unroll
        for (int j = 0; j < 8; j++) {
            ulonglong2 a = ar[j];
            fma2(accL[2 * j], a.x, wL); fma2(accL[2 * j + 1], a.y, wL);
            fma2(accH[2 * j], a.x, wH); fma2(accH[2 * j + 1], a.y, wH);
        }
    }
    __syncwarp();
    // relu + bias -> rows l and l+32 (own columns), conflict-free STS.128
    {
        float bL = b1[l], bH = b1[32 + l];
        float4* rowL = (float4*)(smT + (size_t)l * SPW + ebase);
        float4* rowH = (float4*)(smT + (size_t)(32 + l) * SPW + ebase);
#pragma unroll
        for (int j = 0; j < 8; j++) {
            float2 v0 = unpack2(accL[2 * j]), v1 = unpack2(accL[2 * j + 1]);
            float4 o;
            o.x = fmaxf(v0.x + bL, 0.f); o.y = fmaxf(v0.y + bL, 0.f);
            o.z = fmaxf(v1.x + bL, 0.f); o.w = fmaxf(v1.y + bL, 0.f);
            rowL[j] = o;
            float2 u0 = unpack2(accH[2 * j]), u1 = unpack2(accH[2 * j + 1]);
            float4 p;
            p.x = fmaxf(u0.x + bH, 0.f); p.y = fmaxf(u0.y + bH, 0.f);
            p.z = fmaxf(u1.x + bH, 0.f); p.w = fmaxf(u1.y + bH, 0.f);
            rowH[j] = p;
        }
    }
    __syncwarp();

    // ---- layer 2: K=64 ----
#pragma unroll
    for (int j = 0; j < 16; j++) { accL[j] = 0ull; accH[j] = 0ull; }
#pragma unroll 2
    for (int k = 0; k < 64; k++) {
        float wl = W2[k * 64 + l];
        float wh = W2[k * 64 + 32 + l];
        ull wL = pack2(wl, wl), wH = pack2(wh, wh);
        const ulonglong2* ar = (const ulonglong2*)(base + k * SPW);
#pragma unroll
        for (int j = 0; j < 8; j++) {
            ulonglong2 a = ar[j];
            fma2(accL[2 * j], a.x, wL); fma2(accL[2 * j + 1], a.y, wL);
            fma2(accH[2 * j], a.x, wH); fma2(accH[2 * j + 1], a.y, wH);
        }
    }
    __syncwarp();
    {
        float bL = b2[l], bH = b2[32 + l];
        float4* rowL = (float4*)(smT + (size_t)l * SPW + ebase);
        float4* rowH = (float4*)(smT + (size_t)(32 + l) * SPW + ebase);
#pragma unroll
        for (int j = 0; j < 8; j++) {
            float2 v0 = unpack2(accL[2 * j]), v1 = unpack2(accL[2 * j + 1]);
            float4 o;
            o.x = fmaxf(v0.x + bL, 0.f); o.y = fmaxf(v0.y + bL, 0.f);
            o.z = fmaxf(v1.x + bL, 0.f); o.w = fmaxf(v1.y + bL, 0.f);
            rowL[j] = o;
            float2 u0 = unpack2(accH[2 * j]), u1 = unpack2(accH[2 * j + 1]);
            float4 p;
            p.x = fmaxf(u0.x + bH, 0.f); p.y = fmaxf(u0.y + bH, 0.f);
            p.z = fmaxf(u1.x + bH, 0.f); p.w = fmaxf(u1.y + bH, 0.f);
            rowH[j] = p;
        }
    }
    __syncwarp();

    // ---- layer 3: K=64, N=32, lane owns out l ----
    ull acc3[16];
#pragma unroll
    for (int j = 0; j < 16; j++) acc3[j] = 0ull;
#pragma unroll 2
    for (int k = 0; k < 64; k++) {
        float w = W3[k * 32 + l];
        ull ws = pack2(w, w);
        const ulonglong2* ar = (const ulonglong2*)(base + k * SPW);
#pragma unroll
        for (int j = 0; j < 8; j++) {
            ulonglong2 a = ar[j];
            fma2(acc3[2 * j], a.x, ws); fma2(acc3[2 * j + 1], a.y, ws);
        }
    }
    __syncwarp();
    // store e_new (bias, no relu) -> rows 0..31 (own columns)
    {
        float b3l = b3[l];
        float4* row = (float4*)(smT + (size_t)l * SPW + ebase);
#pragma unroll
        for (int j = 0; j < 8; j++) {
            float2 v0 = unpack2(acc3[2 * j]), v1 = unpack2(acc3[2 * j + 1]);
            float4 o;
            o.x = v0.x + b3l; o.y = v0.y + b3l;
            o.z = v1.x + b3l; o.w = v1.y + b3l;
            row[j] = o;
        }
    }
    __syncwarp();

    // ---- per-thread epilogue on edge t: residual + agg ----
    {
        float* eo = g_e[layer + 1] + (size_t)eid * DD;
        float* ag = g_agg + (size_t)dn * DD;
#pragma unroll
        for (int c = 0; c < 32; c += 2) {
            float n0 = smT[(size_t)c * SPW + t];
            float n1 = smT[(size_t)(c + 1) * SPW + t];
            float i0 = smT[(size_t)(64 + c) * SPW + t];
            float i1 = smT[(size_t)(64 + c + 1) * SPW + t];
            float2 o;
            o.x = 0.5f * i0 + 0.5f * n0;
            o.y = 0.5f * i1 + 0.5f * n1;
            *(float2*)&eo[c] = o;
            red_add_v2(&ag[c], n0, n1);
        }
    }
}

// =====================================================================
// R3 kernels below (known good): encoders, obj, final, utilities
// =====================================================================

__device__ __forceinline__ void st4col(float* smT, int row, int e, float4 v) {
    smT[(row + 0) * SP + e] = v.x;
    smT[(row + 1) * SP + e] = v.y;
    smT[(row + 2) * SP + e] = v.z;
    smT[(row + 3) * SP + e] = v.w;
}
__device__ __forceinline__ void tile_fma8(float4 a, const ull* wp, ull acc[4][4]) {
    ull w0 = wp[0], w1 = wp[1], w2 = wp[2], w3 = wp[3];
    ull a0 = pack2(a.x, a.x), a1 = pack2(a.y, a.y), a2 = pack2(a.z, a.z), a3 = pack2(a.w, a.w);
    fma2(acc[0][0], a0, w0); fma2(acc[0][1], a0, w1); fma2(acc[0][2], a0, w2); fma2(acc[0][3], a0, w3);
    fma2(acc[1][0], a1, w0); fma2(acc[1][1], a1, w1); fma2(acc[1][2], a1, w2); fma2(acc[1][3], a1, w3);
    fma2(acc[2][0], a2, w0); fma2(acc[2][1], a2, w1); fma2(acc[2][2], a2, w2); fma2(acc[2][3], a2, w3);
    fma2(acc[3][0], a3, w0); fma2(acc[3][1], a3, w1); fma2(acc[3][2], a3, w2); fma2(acc[3][3], a3, w3);
}
__device__ __forceinline__ void init_bias8(ull acc[4][4], const float* b, int og) {
#pragma unroll
    for (int j = 0; j < 4; j++) {
        ull bj = pack2(b[og * 8 + 2 * j], b[og * 8 + 2 * j + 1]);
#pragma unroll
        for (int i = 0; i < 4; i++) acc[i][j] = bj;
    }
}
__device__ __forceinline__ void relu_writeH(float* smT, ull acc[4][4], int og, int eg) {
#pragma unroll
    for (int j = 0; j < 4; j++) {
        int r0 = (og * 8 + 2 * j) * SP + 4 * eg;
        int r1 = r0 + SP;
#pragma unroll
        for (int i = 0; i < 4; i++) {
            float2 v = unpack2(acc[i][j]);
            smT[r0 + i] = fmaxf(v.x, 0.f);
            smT[r1 + i] = fmaxf(v.y, 0.f);
        }
    }
}
template <int OUTP>
__device__ __forceinline__ void consume1(float a, const float* Wrow, ull* acc) {
    ull a2 = pack2(a, a);
    const ull* w = reinterpret_cast<const ull*>(Wrow);
#pragma unroll
    for (int j = 0; j < OUTP; j++) fma2(acc[j], a2, w[j]);
}
template <int OUTP>
__device__ __forceinline__ void consume4(float4 v, const float* W, int k0, ull* acc) {
    consume1<OUTP>(v.x, W + (size_t)(k0 + 0) * (2 * OUTP), acc);
    consume1<OUTP>(v.y, W + (size_t)(k0 + 1) * (2 * OUTP), acc);
    consume1<OUTP>(v.z, W + (size_t)(k0 + 2) * (2 * OUTP), acc);
    consume1<OUTP>(v.w, W + (size_t)(k0 + 3) * (2 * OUTP), acc);
}
template <int OUTP>
__device__ __forceinline__ void init_acc(ull* acc, const float* b) {
#pragma unroll
    for (int j = 0; j < OUTP; j++) acc[j] = pack2(b[2 * j], b[2 * j + 1]);
}
template <int OUTP>
__device__ __forceinline__ void init_zero(ull* acc) {
#pragma unroll
    for (int j = 0; j < OUTP; j++) acc[j] = 0ull;
}
template <int OUTP>
__device__ __forceinline__ void relu_store(const ull* acc, ull* s) {
#pragma unroll
    for (int j = 0; j < OUTP; j++) {
        float2 v = unpack2(acc[j]);
        s[j * 128] = pack2(fmaxf(v.x, 0.f), fmaxf(v.y, 0.f));
    }
}
template <int INP, int OUTP>
__device__ __forceinline__ void mlp_scratch(const ull* s, const float* W, ull* acc) {
#pragma unroll 1
    for (int p = 0; p < INP; p++) {
        float2 av = unpack2(s[p * 128]);
        consume1<OUTP>(av.x, W + (size_t)(2 * p) * (2 * OUTP), acc);
        consume1<OUTP>(av.y, W + (size_t)(2 * p + 1) * (2 * OUTP), acc);
    }
}

__global__ __launch_bounds__(128) void node_enc_kernel(const float* __restrict__ x,
                                                       const float* __restrict__ W1,
                                                       const float* __restrict__ W2) {
    extern __shared__ float sm[];
    float* sW1 = sm;
    float* sW2 = sm + 896;
    ull* scr = (ull*)(sm + 2944);
    int t = threadIdx.x;
    coop_load(sW1, W1, 896, t, 128);
    coop_load(sW2, W2, 2048, t, 128);
    __syncthreads();
    int n = blockIdx.x * 128 + t;
    if (n >= N_NODES) return;
    const float* xr = x + (size_t)n * 14;
    ull acc[32]; init_zero<32>(acc);
#pragma unroll 1
    for (int k = 0; k < 14; k++) consume1<32>(xr[k], sW1 + k * 64, acc);
    relu_store<32>(acc, scr + t);
    ull acc2[16]; init_zero<16>(acc2);
    mlp_scratch<32, 16>(scr + t, sW2, acc2);
    float4* ho = (float4*)(g_h + (size_t)n * DD);
#pragma unroll
    for (int q = 0; q < 8; q++) {
        float2 v0 = unpack2(acc2[2 * q]);
        float2 v1 = unpack2(acc2[2 * q + 1]);
        float4 o;
        o.x = fmaxf(v0.x, 0.f); o.y = fmaxf(v0.y, 0.f);
        o.z = fmaxf(v1.x, 0.f); o.w = fmaxf(v1.y, 0.f);
        ho[q] = o;
    }
}

__global__ __launch_bounds__(128) void edge_enc_kernel(const float* __restrict__ ea,
                                                       const float* __restrict__ W1,
                                                       const float* __restrict__ W2) {
    extern __shared__ float sm[];
    float* sW1 = sm;
    float* sW2 = sm + 256;
    ull* scr = (ull*)(sm + 2304);
    int t = threadIdx.x;
    coop_load(sW1, W1, 256, t, 128);
    coop_load(sW2, W2, 2048, t, 128);
    __syncthreads();
    int e = blockIdx.x * 128 + t;
    if (e >= N_EDGES) return;
    float4 av = ((const float4*)ea)[e];
    ull acc[32]; init_zero<32>(acc);
    consume4<32>(av, sW1, 0, acc);
    relu_store<32>(acc, scr + t);
    ull acc2[16]; init_zero<16>(acc2);
    mlp_scratch<32, 16>(scr + t, sW2, acc2);
    float4* eo = (float4*)(g_e[0] + (size_t)e * DD);
#pragma unroll
    for (int q = 0; q < 8; q++) {
        float2 v0 = unpack2(acc2[2 * q]);
        float2 v1 = unpack2(acc2[2 * q + 1]);
        float4 o;
        o.x = fmaxf(v0.x, 0.f); o.y = fmaxf(v0.y, 0.f);
        o.z = fmaxf(v1.x, 0.f); o.w = fmaxf(v1.y, 0.f);
        eo[q] = o;
    }
}

__global__ __launch_bounds__(128) void obj_kernel(const float* __restrict__ W1, const float* __restrict__ b1,
                                                  const float* __restrict__ W2, const float* __restrict__ b2,
                                                  const float* __restrict__ W3, const float* __restrict__ b3) {
    extern __shared__ float sm[];
    float* sW1 = sm;
    float* sW2 = sm + 4096;
    float* sW3 = sm + 8192;
    float* sb1 = sm + 10240;
    float* sb2 = sm + 10304;
    float* sb3 = sm + 10368;
    ull* scr = (ull*)(sm + 10400);
    int t = threadIdx.x;
    coop_load(sW1, W1, 4096, t, 128);
    coop_load(sW2, W2, 4096, t, 128);
    coop_load(sW3, W3, 2048, t, 128);
    coop_load(sb1, b1, 64, t, 128);
    coop_load(sb2, b2, 64, t, 128);
    coop_load(sb3, b3, 32, t, 128);
    __syncthreads();
    int n = blockIdx.x * 128 + t;
    if (n >= N_NODES) return;
    const float4* hp = (const float4*)(g_h + (size_t)n * DD);
    float4 hr[8];
#pragma unroll
    for (int q = 0; q < 8; q++) hr[q] = hp[q];
    ull acc[32]; init_acc<32>(acc, sb1);
#pragma unroll 1
    for (int q = 0; q < 8; q++) { consume4<32>(hr[q], sW1, q * 4, acc); }
    const float4* ap = (const float4*)(g_agg + (size_t)n * DD);
#pragma unroll 1
    for (int q = 0; q < 8; q++) { float4 v = ap[q]; consume4<32>(v, sW1, 32 + q * 4, acc); }
    relu_store<32>(acc, scr + t);
    ull acc2[32]; init_acc<32>(acc2, sb2);
    mlp_scratch<32, 32>(scr + t, sW2, acc2);
    relu_store<32>(acc2, scr + t);
    ull acc3[16]; init_acc<16>(acc3, sb3);
    mlp_scratch<32, 16>(scr + t, sW3, acc3);
    float4* ho = (float4*)(g_h + (size_t)n * DD);
#pragma unroll
    for (int q = 0; q < 8; q++) {
        float2 v0 = unpack2(acc3[2 * q]);
        float2 v1 = unpack2(acc3[2 * q + 1]);
        float4 o;
        o.x = 0.5f * hr[q].x + 0.5f * v0.x;
        o.y = 0.5f * hr[q].y + 0.5f * v0.y;
        o.z = 0.5f * hr[q].z + 0.5f * v1.x;
        o.w = 0.5f * hr[q].w + 0.5f * v1.y;
        ho[q] = o;
    }
}

__global__ __launch_bounds__(256, 2) void final_tile_kernel(const int* __restrict__ ei,
        const float* __restrict__ W1, const float* __restrict__ b1,
        const float* __restrict__ W2, const float* __restrict__ b2,
        const float* __restrict__ W3, const float* __restrict__ b3,
        float* __restrict__ out) {
    extern __shared__ float sm[];
    float* sW1 = sm;                    // 6144 (staged half of 192x64)
    float* sW2 = sm + 6144;             // 4096
    float* sW3 = sm + 10240;            // 64
    float* sb1 = sm + 10304;            // 64
    float* sb2 = sm + 10368;            // 64
    float* sb3 = sm + 10432;            // 1 (+3 pad)
    float* smT = sm + 10436;            // 96*SP  (16B aligned)

    int t = threadIdx.x;
    coop_load(sW1, W1, 6144, t, 256);
    coop_load(sW2, W2, 4096, t, 256);
    coop_load(sW3, W3, 64, t, 256);
    coop_load(sb1, b1, 64, t, 256);
    coop_load(sb2, b2, 64, t, 256);
    if (t == 0) sb3[0] = b3[0];

    int blk = blockIdx.x * 128;
    int e = t & 127, part = t >> 7;
    int eid = blk + e;
    int s = ei[eid];
    int d = ei[N_EDGES + eid];

    {
        const float4* hs = (const float4*)(g_h + (size_t)s * DD);
        const float4* hd = (const float4*)(g_h + (size_t)d * DD);
        const float4* e1 = (const float4*)(g_e[1] + (size_t)eid * DD);
        if (part == 0) {
#pragma unroll
            for (int q = 0; q < 8; q++) st4col(smT, 4 * q, e, hs[q]);
#pragma unroll
            for (int q = 0; q < 4; q++) st4col(smT, 32 + 4 * q, e, hd[q]);
        } else {
#pragma unroll
            for (int q = 4; q < 8; q++) st4col(smT, 32 + 4 * q, e, hd[q]);
#pragma unroll
            for (int q = 0; q < 8; q++) st4col(smT, 64 + 4 * q, e, e1[q]);
        }
    }
    __syncthreads();

    int eg = t & 31, og = t >> 5;
    ull acc[4][4];
    init_bias8(acc, sb1, og);
#pragma unroll 2
    for (int k = 0; k < 96; k++) {
        float4 a = *(const float4*)&smT[k * SP + 4 * eg];
        tile_fma8(a, (const ull*)&sW1[k * 64 + og * 8], acc);
    }
    __syncthreads();

    {
        const float4* e2 = (const float4*)(g_e[2] + (size_t)eid * DD);
        const float4* e3 = (const float4*)(g_e[3] + (size_t)eid * DD);
        const float4* e4 = (const float4*)(g_e[4] + (size_t)eid * DD);
        if (part == 0) {
#pragma unroll
            for (int q = 0; q < 8; q++) st4col(smT, 4 * q, e, e2[q]);
#pragma unroll
            for (int q = 0; q < 4; q++) st4col(smT, 32 + 4 * q, e, e3[q]);
        } else {
#pragma unroll
            for (int q = 4; q < 8; q++) st4col(smT, 32 + 4 * q, e, e3[q]);
#pragma unroll
            for (int q = 0; q < 8; q++) st4col(smT, 64 + 4 * q, e, e4[q]);
        }
    }
    coop_load(sW1, W1 + 96 * 64, 6144, t, 256);
    __syncthreads();

#pragma unroll 2
    for (int k = 0; k < 96; k++) {
        float4 a = *(const float4*)&smT[k * SP + 4 * eg];
        tile_fma8(a, (const ull*)&sW1[k * 64 + og * 8], acc);
    }
    __syncthreads();
    relu_writeH(smT, acc, og, eg);
    __syncthreads();

    init_bias8(acc, sb2, og);
#pragma unroll 2
    for (int k = 0; k < 64; k++) {
        float4 a = *(const float4*)&smT[k * SP + 4 * eg];
        tile_fma8(a, (const ull*)&sW2[k * 64 + og * 8], acc);
    }
    __syncthreads();
    relu_writeH(smT, acc, og, eg);
    __syncthreads();

    if (t < 128) {
        float logit = sb3[0];
#pragma unroll 2
        for (int k = 0; k < 64; k++) logit += smT[k * SP + t] * sW3[k];
        float sig = 1.f / (1.f + expf(-logit));
        out[blk + t] = 1e-3f + (1.f - 2e-3f) * sig;
    }
}

__global__ void zero_agg_kernel() {
    int i = blockIdx.x * 256 + threadIdx.x;
    if (i < N_NODES * DD) g_agg[i] = 0.f;
}

__global__ void writeback_kernel(float* __restrict__ out) {
    size_t i = (size_t)blockIdx.x * 256 + threadIdx.x;
    if (i < (size_t)N_NODES * DD) out[(size_t)N_EDGES + i] = g_h[i];
    if (i < (size_t)N_EDGES * DD) out[(size_t)N_EDGES + (size_t)N_NODES * DD + i] = g_e[4][i];
}

// ---------------- launch ----------------
extern "C" void kernel_launch(void* const* d_in, const int* in_sizes, int n_in,
                              void* d_out, int out_size) {
    const float* x      = (const float*)d_in[0];
    const int*   ei     = (const int*)d_in[1];
    const float* ea     = (const float*)d_in[2];
    const float* enW1   = (const float*)d_in[3];
    const float* enW2   = (const float*)d_in[4];
    const float* eeW1   = (const float*)d_in[5];
    const float* eeW2   = (const float*)d_in[6];
    const float* rW1    = (const float*)d_in[7];
    const float* rb1    = (const float*)d_in[8];
    const float* rW2    = (const float*)d_in[9];
    const float* rb2    = (const float*)d_in[10];
    const float* rW3    = (const float*)d_in[11];
    const float* rb3    = (const float*)d_in[12];
    const float* oW1    = (const float*)d_in[13];
    const float* ob1    = (const float*)d_in[14];
    const float* oW2    = (const float*)d_in[15];
    const float* ob2    = (const float*)d_in[16];
    const float* oW3    = (const float*)d_in[17];
    const float* ob3    = (const float*)d_in[18];
    const float* wW1    = (const float*)d_in[19];
    const float* wb1    = (const float*)d_in[20];
    const float* wW2    = (const float*)d_in[21];
    const float* wb2    = (const float*)d_in[22];
    const float* wW3    = (const float*)d_in[23];
    const float* wb3    = (const float*)d_in[24];
    float* out = (float*)d_out;

    const int NODE_SMEM = 2944 * 4 + 128 * 32 * 8;   // 44544
    const int EDGE_SMEM = 2304 * 4 + 128 * 32 * 8;   // 41984
    const int OBJ_SMEM  = 10400 * 4 + 128 * 32 * 8;  // 74368
    const int REL_SMEM  = 96 * SPW * 4;              // 99840
    const int FIN_SMEM  = (10436 + 96 * SP) * 4;     // ~94KB

    cudaFuncSetAttribute(node_enc_kernel, cudaFuncAttributeMaxDynamicSharedMemorySize, NODE_SMEM);
    cudaFuncSetAttribute(edge_enc_kernel, cudaFuncAttributeMaxDynamicSharedMemorySize, EDGE_SMEM);
    cudaFuncSetAttribute(obj_kernel, cudaFuncAttributeMaxDynamicSharedMemorySize, OBJ_SMEM);
    cudaFuncSetAttribute(rel_gemm_kernel, cudaFuncAttributeMaxDynamicSharedMemorySize, REL_SMEM);
    cudaFuncSetAttribute(final_tile_kernel, cudaFuncAttributeMaxDynamicSharedMemorySize, FIN_SMEM);

    int nodeBlocks = (N_NODES + 127) / 128;        // 391
    int edgeBlocks128 = (N_EDGES + 127) / 128;     // 6250
    int relBlocks = N_EDGES / 256;                 // 3125 exact
    int finBlocks = N_EDGES / 128;                 // 6250 exact

    node_enc_kernel<<<nodeBlocks, 128, NODE_SMEM>>>(x, enW1, enW2);
    edge_enc_kernel<<<edgeBlocks128, 128, EDGE_SMEM>>>(ea, eeW1, eeW2);

    for (int l = 0; l < L_LAYERS; l++) {
        zero_agg_kernel<<<(N_NODES * DD + 255) / 256, 256>>>();
        rel_gemm_kernel<<<relBlocks, 256, REL_SMEM>>>(ei, l,
            rW1 + (size_t)l * 96 * 64, rb1 + (size_t)l * 64,
            rW2 + (size_t)l * 64 * 64, rb2 + (size_t)l * 64,
            rW3 + (size_t)l * 64 * 32, rb3 + (size_t)l * 32);
        obj_kernel<<<nodeBlocks, 128, OBJ_SMEM>>>(
            oW1 + (size_t)l * 64 * 64, ob1 + (size_t)l * 64,
            oW2 + (size_t)l * 64 * 64, ob2 + (size_t)l * 64,
            oW3 + (size_t)l * 64 * 32, ob3 + (size_t)l * 32);
    }

    final_tile_kernel<<<finBlocks, 256, FIN_SMEM>>>(ei, wW1, wb1, wW2, wb2, wW3, wb3, out);

    writeback_kernel<<<((size_t)N_EDGES * DD + 255) / 256, 256>>>(out);
}